// round 1
// baseline (speedup 1.0000x reference)
#include <cuda_runtime.h>

#define NN 8192
#define NE 16384
#define DD 128
#define RR 64
#define BB 16
#define MAXC 32          // supports up to 4096 edges per relation (actual ~256 +/- 16)
#define XS_STRIDE 129    // conflict-free per-lane x rows in smem

// ---------------- device scratch (no allocations allowed) ----------------
__device__ __align__(16) float g_fullW[RR*DD*DD];   // 4 MB
__device__ __align__(16) float g_swT[DD*DD];        // self_weight transposed
__device__ int   g_comb[NN*RR];                     // (tgt,rel) bucket counts
__device__ float g_inv[NE];                         // per-edge 1/count
__device__ int   g_src[NE], g_tgt[NE], g_rel[NE];
__device__ int   g_relcnt[RR], g_reloff[RR], g_cursor[RR];
__device__ int   g_sorted[NE];
__device__ int   g_is64;

// ---------------- prep kernels ----------------
__global__ void k_zero() {
    int i = blockIdx.x * blockDim.x + threadIdx.x;
    int stride = gridDim.x * blockDim.x;
    for (int k = i; k < NN*RR; k += stride) g_comb[k] = 0;
    if (i < RR) g_relcnt[i] = 0;
}

// Detect whether index tensors are int64 (high words all zero) or int32.
__global__ void k_sniff(const unsigned int* __restrict__ ei) {
    __shared__ int nz;
    if (threadIdx.x == 0) nz = 0;
    __syncthreads();
    int any = 0;
    for (int k = threadIdx.x; k < 2048; k += blockDim.x)
        if (ei[2*k + 1] != 0u) any = 1;
    if (any) atomicOr(&nz, 1);
    __syncthreads();
    if (threadIdx.x == 0) g_is64 = (nz == 0) ? 1 : 0;
}

__global__ void k_decode(const void* __restrict__ dep, const void* __restrict__ ei) {
    int e = blockIdx.x * blockDim.x + threadIdx.x;
    if (e >= NE) return;
    int rel, s, t;
    if (g_is64) {
        rel = (int)((const long long*)dep)[e];
        s   = (int)((const long long*)ei)[e];
        t   = (int)((const long long*)ei)[NE + e];
    } else {
        rel = ((const int*)dep)[e];
        s   = ((const int*)ei)[e];
        t   = ((const int*)ei)[NE + e];
    }
    g_rel[e] = rel; g_src[e] = s; g_tgt[e] = t;
    atomicAdd(&g_comb[t*RR + rel], 1);
    atomicAdd(&g_relcnt[rel], 1);
}

__global__ void k_inv() {
    int e = blockIdx.x * blockDim.x + threadIdx.x;
    if (e < NE)
        g_inv[e] = 1.0f / (float)g_comb[g_tgt[e]*RR + g_rel[e]];
}

__global__ void k_scan() {  // 1 block, 64 threads: exclusive scan over rel counts
    __shared__ int s[RR];
    int t = threadIdx.x;
    s[t] = g_relcnt[t];
    __syncthreads();
    if (t == 0) { int acc = 0; for (int i = 0; i < RR; i++) { int c = s[i]; s[i] = acc; acc += c; } }
    __syncthreads();
    g_reloff[t] = s[t];
    g_cursor[t] = s[t];
}

__global__ void k_scatter() {
    int e = blockIdx.x * blockDim.x + threadIdx.x;
    if (e >= NE) return;
    int pos = atomicAdd(&g_cursor[g_rel[e]], 1);
    g_sorted[pos] = e;
}

// full_weight[r,i,j] = sum_b w_comp[r,b] * weight[b,i,j].  Block = i, thread = j.
__global__ void k_fullw(const float* __restrict__ weight, const float* __restrict__ wcomp) {
    __shared__ float sc[RR*BB];
    int j = threadIdx.x, i = blockIdx.x;
    for (int k = j; k < RR*BB; k += blockDim.x) sc[k] = wcomp[k];
    float wr[BB];
    #pragma unroll
    for (int b = 0; b < BB; b++) wr[b] = weight[(b*DD + i)*DD + j];
    __syncthreads();
    #pragma unroll 4
    for (int r = 0; r < RR; r++) {
        float acc = 0.f;
        #pragma unroll
        for (int b = 0; b < BB; b++) acc += sc[r*BB + b] * wr[b];
        g_fullW[(r*DD + i)*DD + j] = acc;
    }
}

__global__ void k_swt(const float* __restrict__ sw) {
    int idx = blockIdx.x * blockDim.x + threadIdx.x;
    if (idx < DD*DD) {
        int jrow = idx / DD, i = idx % DD;
        g_swT[i*DD + jrow] = sw[idx];   // swT[i][j] = self_weight[j][i]
    }
}

// ---------------- self projection: out[n,:] = bias + inp[n,:] @ swT ----------------
// block = (128 nodes, jhalf), thread <-> node, 64 output cols in registers.
__global__ void __launch_bounds__(128) k_self(const float* __restrict__ inp,
                                              const float* __restrict__ bias,
                                              float* __restrict__ out) {
    extern __shared__ float sm[];
    float4* Wh4 = (float4*)sm;          // 2048 float4 = 32KB (half of swT)
    float*  xs  = sm + 8192;            // 128 rows, stride 129
    int tid = threadIdx.x;
    int n0  = blockIdx.x * 128;
    int jh  = blockIdx.y;

    const float4* swT4 = (const float4*)g_swT;
    for (int k = tid; k < 2048; k += 128) {
        int i = k >> 4, jj = k & 15;
        Wh4[k] = swT4[i*32 + jh*16 + jj];
    }
    for (int k = tid; k < 128*DD; k += 128)
        xs[(k >> 7)*XS_STRIDE + (k & 127)] = inp[n0*DD + k];
    __syncthreads();

    float4 acc[16];
    #pragma unroll
    for (int jj = 0; jj < 16; jj++) acc[jj] = make_float4(0.f, 0.f, 0.f, 0.f);

    const float* xrow = xs + tid*XS_STRIDE;
    #pragma unroll 2
    for (int i = 0; i < DD; i++) {
        float x = xrow[i];
        const float4* wr = Wh4 + i*16;
        #pragma unroll
        for (int jj = 0; jj < 16; jj++) {
            float4 w = wr[jj];
            acc[jj].x += x*w.x; acc[jj].y += x*w.y;
            acc[jj].z += x*w.z; acc[jj].w += x*w.w;
        }
    }
    float* op = out + (n0 + tid)*DD + jh*64;
    #pragma unroll
    for (int jj = 0; jj < 16; jj++) {
        int col = jh*64 + jj*4;
        float4 v;
        v.x = acc[jj].x + bias[col + 0];
        v.y = acc[jj].y + bias[col + 1];
        v.z = acc[jj].z + bias[col + 2];
        v.w = acc[jj].w + bias[col + 3];
        ((float4*)op)[jj] = v;
    }
}

// ---------------- edge aggregation ----------------
// block = (rel, jhalf, chunk of 128 edges of that rel), thread <-> edge.
// x rows are premultiplied by 1/count; 64 accumulators per thread; atomicAdd into out.
__global__ void __launch_bounds__(128) k_edge(const float* __restrict__ inp,
                                              float* __restrict__ out) {
    int r  = blockIdx.z;
    int jh = blockIdx.y;
    int c  = blockIdx.x;
    int cnt = g_relcnt[r];
    if (c*128 >= cnt) return;

    extern __shared__ float sm[];
    float4* Wh4  = (float4*)sm;                    // 32KB: W[rel] half
    float*  xs   = sm + 8192;                      // 128 x rows, stride 129
    int*   s_src = (int*)(xs + 128*XS_STRIDE);
    int*   s_tgt = s_src + 128;
    float* s_inv = (float*)(s_tgt + 128);

    int tid = threadIdx.x;
    int off = g_reloff[r];
    int le  = c*128 + tid;
    bool valid = le < cnt;
    int e = valid ? g_sorted[off + le] : g_sorted[off];
    s_src[tid] = g_src[e];
    s_tgt[tid] = g_tgt[e];
    s_inv[tid] = valid ? g_inv[e] : 0.f;

    const float4* fw4 = ((const float4*)g_fullW) + (size_t)r * 4096;
    for (int k = tid; k < 2048; k += 128) {
        int i = k >> 4, jj = k & 15;
        Wh4[k] = fw4[i*32 + jh*16 + jj];
    }
    __syncthreads();

    // cooperative, coalesced gather of x rows (pre-scaled by 1/count)
    for (int e2 = 0; e2 < 128; e2++)
        xs[e2*XS_STRIDE + tid] = inp[s_src[e2]*DD + tid] * s_inv[e2];
    __syncthreads();

    // warps with no valid edge skip the FMA loop entirely
    if ((c*128 + (tid & ~31)) < cnt) {
        float4 acc[16];
        #pragma unroll
        for (int jj = 0; jj < 16; jj++) acc[jj] = make_float4(0.f, 0.f, 0.f, 0.f);

        const float* xrow = xs + tid*XS_STRIDE;
        #pragma unroll 2
        for (int i = 0; i < DD; i++) {
            float x = xrow[i];
            const float4* wr = Wh4 + i*16;
            #pragma unroll
            for (int jj = 0; jj < 16; jj++) {
                float4 w = wr[jj];
                acc[jj].x += x*w.x; acc[jj].y += x*w.y;
                acc[jj].z += x*w.z; acc[jj].w += x*w.w;
            }
        }
        if (valid) {
            float* op = out + s_tgt[tid]*DD + jh*64;
            #pragma unroll
            for (int jj = 0; jj < 16; jj++) {
                atomicAdd(op + jj*4 + 0, acc[jj].x);
                atomicAdd(op + jj*4 + 1, acc[jj].y);
                atomicAdd(op + jj*4 + 2, acc[jj].z);
                atomicAdd(op + jj*4 + 3, acc[jj].w);
            }
        }
    }
}

// ---------------- launch ----------------
extern "C" void kernel_launch(void* const* d_in, const int* in_sizes, int n_in,
                              void* d_out, int out_size) {
    const float* inp    = (const float*)d_in[0];
    const void*  dep    = d_in[1];
    const void*  ei     = d_in[2];
    const float* weight = (const float*)d_in[3];
    const float* wcomp  = (const float*)d_in[4];
    const float* sw     = (const float*)d_in[5];
    const float* bias   = (const float*)d_in[6];
    float* out = (float*)d_out;

    const int SMEM = 8192*4 + 128*XS_STRIDE*4 + 128*4*3;   // 100352 bytes
    cudaFuncSetAttribute(k_self, cudaFuncAttributeMaxDynamicSharedMemorySize, SMEM);
    cudaFuncSetAttribute(k_edge, cudaFuncAttributeMaxDynamicSharedMemorySize, SMEM);

    k_zero<<<512, 256>>>();
    k_sniff<<<1, 256>>>((const unsigned int*)ei);
    k_decode<<<NE/256, 256>>>(dep, ei);
    k_inv<<<NE/256, 256>>>();
    k_scan<<<1, RR>>>();
    k_scatter<<<NE/256, 256>>>();
    k_fullw<<<DD, 128>>>(weight, wcomp);
    k_swt<<<(DD*DD + 255)/256, 256>>>(sw);
    k_self<<<dim3(NN/128, 2), 128, SMEM>>>(inp, bias, out);
    k_edge<<<dim3(MAXC, 2, RR), 128, SMEM>>>(inp, out);
}

// round 2
// speedup vs baseline: 1.0706x; 1.0706x over previous
#include <cuda_runtime.h>

#define NN 8192
#define NE 16384
#define DD 128
#define RR 64
#define BB 16
#define NCHUNK 8            // supports up to 1024 edges/relation (actual ~256±16)
#define XS_STRIDE 129       // odd stride -> conflict-free per-lane x rows

typedef unsigned long long u64;

// ---------------- device scratch (no allocations allowed) ----------------
__device__ __align__(16) float g_fullW[RR*DD*DD];   // 4 MB expanded basis
__device__ __align__(16) float g_swT[DD*DD];        // self_weight transposed
__device__ int g_comb[NN*RR];                       // (tgt,rel) bucket counts
__device__ int g_src[NE], g_tgt[NE], g_rel[NE];
__device__ int g_relcnt[RR], g_reloff[RR], g_cursor[RR];
__device__ int g_sorted[NE];
__device__ int g_is64;

// ---------------- packed fp32x2 + vector reduction helpers ----------------
__device__ __forceinline__ u64 pack2(float x) {
    u64 r; asm("mov.b64 %0, {%1, %1};" : "=l"(r) : "f"(x)); return r;
}
__device__ __forceinline__ void ffma2(u64& d, u64 a, u64 b) {
    asm("fma.rn.f32x2 %0, %1, %2, %0;" : "+l"(d) : "l"(a), "l"(b));
}
__device__ __forceinline__ float2 unpack2(u64 v) {
    float2 f; asm("mov.b64 {%0, %1}, %2;" : "=f"(f.x), "=f"(f.y) : "l"(v)); return f;
}
__device__ __forceinline__ void red4(float* p, float a, float b, float c, float d) {
    asm volatile("red.global.add.v4.f32 [%0], {%1,%2,%3,%4};"
                 :: "l"(p), "f"(a), "f"(b), "f"(c), "f"(d) : "memory");
}

// ---------------- kernel 1: zero scratch + output, sniff index width ----------------
__global__ void k_prep(float* __restrict__ out, const unsigned int* __restrict__ ei) {
    __shared__ int nz;
    int i = blockIdx.x * blockDim.x + threadIdx.x;
    int stride = gridDim.x * blockDim.x;           // 131072 threads
    int4 z4 = make_int4(0, 0, 0, 0);
    for (int k = i; k < NN*RR/4; k += stride) ((int4*)g_comb)[k] = z4;
    float4 f4 = make_float4(0.f, 0.f, 0.f, 0.f);
    for (int k = i; k < NN*DD/4; k += stride) ((float4*)out)[k] = f4;
    if (i < RR) g_relcnt[i] = 0;
    if (blockIdx.x == 0) {                          // int64-vs-int32 sniff
        if (threadIdx.x == 0) nz = 0;
        __syncthreads();
        int any = 0;
        for (int k = threadIdx.x; k < 2048; k += blockDim.x)
            if (ei[2*k + 1] != 0u) any = 1;
        if (any) atomicOr(&nz, 1);
        __syncthreads();
        if (threadIdx.x == 0) g_is64 = (nz == 0) ? 1 : 0;
    }
}

// ---------------- kernel 2: decode indices + bucket/relation counts ----------------
__global__ void k_decode(const void* __restrict__ dep, const void* __restrict__ ei) {
    int e = blockIdx.x * blockDim.x + threadIdx.x;
    if (e >= NE) return;
    int rel, s, t;
    if (g_is64) {
        rel = (int)((const long long*)dep)[e];
        s   = (int)((const long long*)ei)[e];
        t   = (int)((const long long*)ei)[NE + e];
    } else {
        rel = ((const int*)dep)[e];
        s   = ((const int*)ei)[e];
        t   = ((const int*)ei)[NE + e];
    }
    g_rel[e] = rel; g_src[e] = s; g_tgt[e] = t;
    atomicAdd(&g_comb[t*RR + rel], 1);
    atomicAdd(&g_relcnt[rel], 1);
}

// ---------------- kernel 3: relation scan + basis expansion + W^T ----------------
__global__ void k_scanw(const float* __restrict__ weight,
                        const float* __restrict__ wcomp,
                        const float* __restrict__ sw) {
    __shared__ int   s[RR];
    __shared__ float sc[RR*BB];
    int bid = blockIdx.x, tid = threadIdx.x;
    if (bid == 0) {                                 // exclusive scan of rel counts
        if (tid < RR) s[tid] = g_relcnt[tid];
        __syncthreads();
        if (tid == 0) { int acc = 0; for (int i = 0; i < RR; i++) { int c = s[i]; s[i] = acc; acc += c; } }
        __syncthreads();
        if (tid < RR) { g_reloff[tid] = s[tid]; g_cursor[tid] = s[tid]; }
    } else if (bid <= DD) {                         // full_weight[r,i,:] for i = bid-1
        int i = bid - 1, j = tid;
        for (int k = j; k < RR*BB; k += blockDim.x) sc[k] = wcomp[k];
        float wr[BB];
        #pragma unroll
        for (int b = 0; b < BB; b++) wr[b] = weight[(b*DD + i)*DD + j];
        __syncthreads();
        #pragma unroll 4
        for (int r = 0; r < RR; r++) {
            float a = 0.f;
            #pragma unroll
            for (int b = 0; b < BB; b++) a += sc[r*BB + b] * wr[b];
            g_fullW[(r*DD + i)*DD + j] = a;
        }
    } else {                                        // self_weight transpose, 4 rows/block
        int j0 = (bid - 129) * 4;
        #pragma unroll
        for (int jj = 0; jj < 4; jj++)
            g_swT[tid*DD + j0 + jj] = sw[(j0 + jj)*DD + tid];
    }
}

// ---------------- kernel 4: counting-sort scatter by relation ----------------
__global__ void k_scatter() {
    int e = blockIdx.x * blockDim.x + threadIdx.x;
    if (e >= NE) return;
    int pos = atomicAdd(&g_cursor[g_rel[e]], 1);
    g_sorted[pos] = e;
}

// ---------------- kernel 5: fused edge-matvec + self-projection ----------------
// grid = (64, 2, NCHUNK+1).  z < NCHUNK: edge path, rel = blockIdx.x, chunk = z.
// z == NCHUNK: self path, node-chunk = blockIdx.x.  All results red.add into
// pre-zeroed out.  Thread <-> (edge|node) row, 64 output cols in 32 packed-f32x2 accs.
__global__ void __launch_bounds__(128) k_main(const float* __restrict__ inp,
                                              const float* __restrict__ bias,
                                              float* __restrict__ out) {
    int z  = blockIdx.z;
    int jh = blockIdx.y;
    bool is_self = (z == NCHUNK);
    int rel   = blockIdx.x;                          // also node-chunk for self
    int cnt   = is_self ? NN : g_relcnt[rel];
    int base  = (is_self ? rel : z) * 128;           // row offset within segment
    if (base >= cnt) return;

    extern __shared__ float sm[];
    float4* Wh4  = (float4*)sm;                      // 32KB: half of W (64 cols)
    float*  xs   = sm + 8192;                        // 128 rows, stride 129
    int*   s_src = (int*)(xs + 128*XS_STRIDE);

    int tid = threadIdx.x;
    int le  = base + tid;
    bool valid = le < cnt;

    int   tgt_t;
    float inv_t;
    if (is_self) {
        s_src[tid] = le;                             // always valid (NN = 64*128)
        tgt_t = le;
        inv_t = 1.f;
    } else {
        int off = g_reloff[rel];
        int e = g_sorted[off + (valid ? le - 0 : base)];
        int t = g_tgt[e];
        s_src[tid] = g_src[e];
        tgt_t = t;
        inv_t = 1.0f / (float)g_comb[t*RR + rel];
    }

    const float4* wsrc = is_self ? (const float4*)g_swT
                                 : ((const float4*)g_fullW) + (size_t)rel * 4096;
    for (int k = tid; k < 2048; k += 128) {
        int i = k >> 4, jj = k & 15;
        Wh4[k] = wsrc[i*32 + jh*16 + jj];
    }
    __syncthreads();

    // cooperative coalesced gather of the 128 x-rows (unrolled for MLP)
    #pragma unroll 16
    for (int e2 = 0; e2 < 128; e2++)
        xs[e2*XS_STRIDE + tid] = inp[s_src[e2]*DD + tid];
    __syncthreads();

    if ((base + (tid & ~31)) >= cnt) return;         // fully-invalid warps bail

    u64 acc[32];
    #pragma unroll
    for (int a = 0; a < 32; a++) acc[a] = 0ull;

    const float* xrow = xs + tid*XS_STRIDE;
    const ulonglong2* W8 = (const ulonglong2*)Wh4;
    #pragma unroll 2
    for (int i = 0; i < DD; i++) {
        u64 xx = pack2(xrow[i]);
        const ulonglong2* wr = W8 + i*16;
        #pragma unroll
        for (int jj = 0; jj < 16; jj++) {
            ulonglong2 w = wr[jj];
            ffma2(acc[2*jj],     xx, w.x);
            ffma2(acc[2*jj + 1], xx, w.y);
        }
    }

    if (!valid) return;
    float* op = out + (size_t)tgt_t*DD + jh*64;
    const float* bp = bias + jh*64;
    #pragma unroll
    for (int q = 0; q < 16; q++) {
        float2 a = unpack2(acc[2*q]);
        float2 b = unpack2(acc[2*q + 1]);
        float v0 = a.x*inv_t, v1 = a.y*inv_t, v2 = b.x*inv_t, v3 = b.y*inv_t;
        if (is_self) { v0 += bp[4*q]; v1 += bp[4*q+1]; v2 += bp[4*q+2]; v3 += bp[4*q+3]; }
        red4(op + 4*q, v0, v1, v2, v3);
    }
}

// ---------------- launch ----------------
extern "C" void kernel_launch(void* const* d_in, const int* in_sizes, int n_in,
                              void* d_out, int out_size) {
    const float* inp    = (const float*)d_in[0];
    const void*  dep    = d_in[1];
    const void*  ei     = d_in[2];
    const float* weight = (const float*)d_in[3];
    const float* wcomp  = (const float*)d_in[4];
    const float* sw     = (const float*)d_in[5];
    const float* bias   = (const float*)d_in[6];
    float* out = (float*)d_out;

    const int SMEM = 8192*4 + 128*XS_STRIDE*4 + 128*4;   // 99.5 KB
    cudaFuncSetAttribute(k_main, cudaFuncAttributeMaxDynamicSharedMemorySize, SMEM);

    k_prep<<<512, 256>>>(out, (const unsigned int*)ei);
    k_decode<<<NE/256, 256>>>(dep, ei);
    k_scanw<<<161, 128>>>(weight, wcomp, sw);
    k_scatter<<<NE/256, 256>>>();
    k_main<<<dim3(64, 2, NCHUNK + 1), 128, SMEM>>>(inp, bias, out);
}

// round 3
// speedup vs baseline: 1.3158x; 1.2290x over previous
#include <cuda_runtime.h>

#define NN 8192
#define NE 16384
#define DD 128
#define RR 64
#define BB 16
#define GRID 148
#define NTHR 256
#define TROWS 64            // rows (edges/nodes) per tile
#define XS_STRIDE 129       // conflict-free x rows in smem

typedef unsigned long long u64;

// ---------------- device scratch (no allocations allowed) ----------------
__device__ __align__(16) float g_fullW[RR*DD*DD];   // 4 MB expanded basis
__device__ __align__(16) float g_swT[DD*DD];        // self_weight transposed
__device__ int g_comb[NN*RR];                       // (tgt,rel) bucket counts
__device__ int g_cnt8[RR*8];                        // banked relation counters
__device__ int g_off8[RR*8];                        // scanned bank offsets
__device__ int g_relcnt[RR], g_reloff[RR];
__device__ int g_src[NE], g_tgt[NE], g_rel[NE], g_rank[NE];
__device__ int g_sorted[NE];
__device__ int g_tiles[2048], g_ntiles;
__device__ int g_is64;
__device__ int g_bar[8];
__device__ unsigned g_ticket;

// ---------------- helpers ----------------
__device__ __forceinline__ u64 pack2(float x) {
    u64 r; asm("mov.b64 %0, {%1, %1};" : "=l"(r) : "f"(x)); return r;
}
__device__ __forceinline__ void ffma2(u64& d, u64 a, u64 b) {
    asm("fma.rn.f32x2 %0, %1, %2, %0;" : "+l"(d) : "l"(a), "l"(b));
}
__device__ __forceinline__ float2 unpack2(u64 v) {
    float2 f; asm("mov.b64 {%0, %1}, %2;" : "=f"(f.x), "=f"(f.y) : "l"(v)); return f;
}
__device__ __forceinline__ void red4(float* p, float a, float b, float c, float d) {
    asm volatile("red.global.add.v4.f32 [%0], {%1,%2,%3,%4};"
                 :: "l"(p), "f"(a), "f"(b), "f"(c), "f"(d) : "memory");
}
__device__ __forceinline__ int ld_cg(const int* p) {
    int v; asm volatile("ld.global.cg.b32 %0, [%1];" : "=r"(v) : "l"(p) : "memory"); return v;
}
// device-wide barrier: all GRID blocks resident by construction
__device__ __forceinline__ void gbar(int p) {
    __threadfence();
    __syncthreads();
    if (threadIdx.x == 0) {
        atomicAdd(&g_bar[p], 1);
        while (ld_cg(&g_bar[p]) < GRID) __nanosleep(128);
    }
    __syncthreads();
}

// ---------------- the single persistent kernel ----------------
__global__ void __launch_bounds__(NTHR) k_fused(
        const float* __restrict__ inp, const void* __restrict__ dep,
        const void* __restrict__ ei,   const float* __restrict__ weight,
        const float* __restrict__ wcomp, const float* __restrict__ sw,
        const float* __restrict__ bias, float* __restrict__ out) {
    extern __shared__ float sm[];
    float4* sW4   = (float4*)sm;                  // 4096 float4 = 64 KB (full W)
    float*  xs    = sm + 16384;                   // 64 rows * stride 129
    int*    s_src = (int*)(xs + TROWS*XS_STRIDE);
    int*    s_tgt = s_src + TROWS;
    float*  s_inv = (float*)(s_tgt + TROWS);
    int*    s_misc= (int*)(s_inv + TROWS);        // [0]=tile ticket / sniff flag

    const int bid = blockIdx.x, tid = threadIdx.x;
    const int gtid = bid*NTHR + tid, G = GRID*NTHR;

    // ---- phase 0: zero scratch & output, reset ticket, sniff index width ----
    {
        const int4 z4 = make_int4(0,0,0,0);
        for (int k = gtid; k < NN*RR/4; k += G) ((int4*)g_comb)[k] = z4;
        const float4 f4 = make_float4(0.f,0.f,0.f,0.f);
        for (int k = gtid; k < NN*DD/4; k += G) ((float4*)out)[k] = f4;
        if (gtid < RR*8) g_cnt8[gtid] = 0;
        if (gtid == 0) g_ticket = 0u;
        if (bid == 0) {                            // int64-vs-int32 sniff on edge_index
            if (tid == 0) s_misc[0] = 0;
            __syncthreads();
            int any = 0;
            const unsigned* eu = (const unsigned*)ei;
            for (int k = tid; k < 2048; k += NTHR)
                if (eu[2*k + 1] != 0u) any = 1;
            if (any) atomicOr(s_misc, 1);
            __syncthreads();
            if (tid == 0) g_is64 = (s_misc[0] == 0) ? 1 : 0;
        }
    }
    gbar(0);

    // ---- phase 1: decode indices, bucket counts, banked ranks ----
    if (gtid < NE) {
        const int e = gtid;
        int rel, s, t;
        if (g_is64) {
            rel = (int)((const long long*)dep)[e];
            s   = (int)((const long long*)ei)[e];
            t   = (int)((const long long*)ei)[NE + e];
        } else {
            rel = ((const int*)dep)[e];
            s   = ((const int*)ei)[e];
            t   = ((const int*)ei)[NE + e];
        }
        g_rel[e] = rel; g_src[e] = s; g_tgt[e] = t;
        atomicAdd(&g_comb[t*RR + rel], 1);
        const int bank = bid & 7;
        const int rk = atomicAdd(&g_cnt8[rel*8 + bank], 1);
        g_rank[e] = (bank << 16) | rk;
    }
    gbar(1);

    // ---- phase 2: basis expansion + W^T + scan + tile list ----
    if (bid < DD) {                                // full_weight[:, i=bid, :]
        const int i = bid, j = tid & 127, rh = tid >> 7;   // rh splits r-range
        for (int k = tid; k < RR*BB; k += NTHR) sm[k] = wcomp[k];
        float wr[BB];
        #pragma unroll
        for (int b = 0; b < BB; b++) wr[b] = weight[(b*DD + i)*DD + j];
        __syncthreads();
        #pragma unroll 4
        for (int r = rh*32; r < rh*32 + 32; r++) {
            float a = 0.f;
            #pragma unroll
            for (int b = 0; b < BB; b++) a += sm[r*BB + b] * wr[b];
            g_fullW[((size_t)r*DD + i)*DD + j] = a;
        }
    } else if (bid < DD + 16) {                    // self_weight transpose
        const int j0 = (bid - DD)*8 + (tid >> 7)*4;
        const int i = tid & 127;
        #pragma unroll
        for (int jj = 0; jj < 4; jj++)
            g_swT[i*DD + j0 + jj] = sw[(j0 + jj)*DD + i];
    } else if (bid == DD + 16) {                   // scan 512 bank counters + tile list
        if (tid < 32) {
            int vals[16], local = 0;
            #pragma unroll
            for (int k = 0; k < 16; k++) {
                int c = g_cnt8[tid*16 + k];
                vals[k] = local; local += c;
            }
            int x = local;
            #pragma unroll
            for (int d = 1; d < 32; d <<= 1) {
                int y = __shfl_up_sync(0xffffffffu, x, d);
                if ((tid & 31) >= d) x += y;
            }
            const int excl = x - local;
            #pragma unroll
            for (int k = 0; k < 16; k++) g_off8[tid*16 + k] = excl + vals[k];
            __syncwarp();
            if (tid == 0) {
                int nt = 0;
                for (int r = 0; r < RR; r++) {
                    const int start = g_off8[r*8];
                    const int end = (r == RR-1) ? NE : g_off8[(r+1)*8];
                    const int cnt = end - start;
                    g_reloff[r] = start; g_relcnt[r] = cnt;
                    for (int c = 0; c*TROWS < cnt; c++) g_tiles[nt++] = (r << 8) | c;
                }
                g_ntiles = nt;
            }
        }
    }
    gbar(2);

    // ---- phase 3: atomic-free counting-sort scatter ----
    if (gtid < NE) {
        const int e = gtid;
        const int rel = g_rel[e], rb = g_rank[e];
        g_sorted[g_off8[rel*8 + (rb >> 16)] + (rb & 0xffff)] = e;
    }
    gbar(3);

    // ---- phase 4: work-stealing tiled matvec (edges + self) ----
    const int ntotal = 128 + g_ntiles;             // 128 self tiles of 64 nodes
    const int row = tid & 63, jq = tid >> 6;       // 4 col-quarters of 32 cols
    for (;;) {
        __syncthreads();                           // protect smem + s_misc reuse
        if (tid == 0) s_misc[0] = (int)atomicAdd(&g_ticket, 1u);
        __syncthreads();
        const int t = s_misc[0];
        if (t >= ntotal) break;

        bool is_self; int rel = 0, base, cnt, off = 0;
        if (t < 128) { is_self = true;  base = t*TROWS; cnt = NN; }
        else {
            const int tt = g_tiles[t - 128];
            rel = tt >> 8; base = (tt & 255)*TROWS;
            cnt = g_relcnt[rel]; off = g_reloff[rel];
            is_self = false;
        }

        if (tid < TROWS) {                         // per-row metadata
            if (is_self) {
                s_src[row] = base + row; s_tgt[row] = base + row; s_inv[row] = 1.f;
            } else {
                const int le = base + row;
                const bool v = le < cnt;
                const int e = g_sorted[off + (v ? le : base)];
                const int sN = g_src[e], tN = g_tgt[e];
                s_src[row] = sN; s_tgt[row] = tN;
                s_inv[row] = v ? 1.0f/(float)g_comb[tN*RR + rel] : 0.f;
            }
        }
        // stage W (full 128x128) into smem
        const float4* wsrc = is_self ? (const float4*)g_swT
                                     : (const float4*)g_fullW + (size_t)rel*4096;
        #pragma unroll 4
        for (int k = tid; k < 4096; k += NTHR) sW4[k] = wsrc[k];
        __syncthreads();

        // coalesced gather of the 64 x-rows
        {
            const int col = tid & 127;
            #pragma unroll 8
            for (int r2 = tid >> 7; r2 < TROWS; r2 += 2)
                xs[r2*XS_STRIDE + col] = inp[(size_t)s_src[r2]*DD + col];
        }
        __syncthreads();

        // warps whose 32 rows are all past cnt skip compute entirely
        if (is_self || base + (tid & 32) < cnt) {
            u64 acc[16];
            #pragma unroll
            for (int a = 0; a < 16; a++) acc[a] = 0ull;
            const float* xrow = xs + row*XS_STRIDE;
            #pragma unroll 2
            for (int i = 0; i < DD; i++) {
                const u64 xx = pack2(xrow[i]);
                const ulonglong2* wr = (const ulonglong2*)(sW4 + i*32 + jq*8);
                #pragma unroll
                for (int jj = 0; jj < 8; jj++) {
                    const ulonglong2 w = wr[jj];
                    ffma2(acc[2*jj],     xx, w.x);
                    ffma2(acc[2*jj + 1], xx, w.y);
                }
            }
            if (is_self || base + row < cnt) {
                const float inv = s_inv[row];
                float* op = out + (size_t)s_tgt[row]*DD + jq*32;
                #pragma unroll
                for (int q = 0; q < 8; q++) {
                    const float2 a = unpack2(acc[2*q]);
                    const float2 b = unpack2(acc[2*q + 1]);
                    float v0 = a.x*inv, v1 = a.y*inv, v2 = b.x*inv, v3 = b.y*inv;
                    if (is_self) {
                        const float4 bb = ((const float4*)bias)[jq*8 + q];
                        v0 += bb.x; v1 += bb.y; v2 += bb.z; v3 += bb.w;
                    }
                    red4(op + 4*q, v0, v1, v2, v3);
                }
            }
        }
    }

    // ---- epilogue: last-arriving block resets barrier counters for replay ----
    __threadfence();
    __syncthreads();
    if (tid == 0) {
        const int a = atomicAdd(&g_bar[7], 1);
        if (a == GRID - 1) {
            #pragma unroll
            for (int p = 0; p < 8; p++) g_bar[p] = 0;
            __threadfence();
        }
    }
}

// ---------------- launch ----------------
extern "C" void kernel_launch(void* const* d_in, const int* in_sizes, int n_in,
                              void* d_out, int out_size) {
    const float* inp    = (const float*)d_in[0];
    const void*  dep    = d_in[1];
    const void*  ei     = d_in[2];
    const float* weight = (const float*)d_in[3];
    const float* wcomp  = (const float*)d_in[4];
    const float* sw     = (const float*)d_in[5];
    const float* bias   = (const float*)d_in[6];
    float* out = (float*)d_out;

    // 64KB W + 64*129*4 xs + meta
    const int SMEM = 16384*4 + TROWS*XS_STRIDE*4 + TROWS*4*3 + 64;
    static int configured = 0;
    cudaFuncSetAttribute(k_fused, cudaFuncAttributeMaxDynamicSharedMemorySize, SMEM);
    (void)configured;

    k_fused<<<GRID, NTHR, SMEM>>>(inp, dep, ei, weight, wcomp, sw, bias, out);
}

// round 4
// speedup vs baseline: 1.6809x; 1.2775x over previous
#include <cuda_runtime.h>

#define NN 8192
#define NE 16384
#define DD 128
#define RR 64
#define BB 16
#define GRID 148
#define NTHR 512
#define TROWS 64            // rows (edges/nodes) per tile
#define XS_STRIDE 132       // 16B-aligned, conflict-free x rows

typedef unsigned long long u64;

// ---------------- device scratch (no allocations allowed) ----------------
__device__ __align__(16) float g_fullW[RR*DD*DD];   // 4 MB expanded basis
__device__ __align__(16) float g_swT[DD*DD];        // self_weight transposed
__device__ int g_comb[NN*RR];                       // (tgt,rel) bucket counts
__device__ int g_cnt8[RR*8];                        // banked relation counters
__device__ int g_off8[RR*8];                        // scanned bank offsets
__device__ int g_relcnt[RR], g_reloff[RR];
__device__ int g_src[NE], g_tgt[NE], g_rel[NE], g_rank[NE];
__device__ int g_sorted[NE];
__device__ int g_tiles[2048], g_ntiles;
__device__ int g_is64;
__device__ int g_bar[8];
__device__ unsigned g_ticket;

// ---------------- helpers ----------------
__device__ __forceinline__ u64 pack2(float x) {
    u64 r; asm("mov.b64 %0, {%1, %1};" : "=l"(r) : "f"(x)); return r;
}
__device__ __forceinline__ void ffma2(u64& d, u64 a, u64 b) {
    asm("fma.rn.f32x2 %0, %1, %2, %0;" : "+l"(d) : "l"(a), "l"(b));
}
__device__ __forceinline__ float2 unpack2(u64 v) {
    float2 f; asm("mov.b64 {%0, %1}, %2;" : "=f"(f.x), "=f"(f.y) : "l"(v)); return f;
}
__device__ __forceinline__ void red4(float* p, float a, float b, float c, float d) {
    asm volatile("red.global.add.v4.f32 [%0], {%1,%2,%3,%4};"
                 :: "l"(p), "f"(a), "f"(b), "f"(c), "f"(d) : "memory");
}
__device__ __forceinline__ int ld_cg(const int* p) {
    int v; asm volatile("ld.global.cg.b32 %0, [%1];" : "=r"(v) : "l"(p) : "memory"); return v;
}
// device-wide barrier: all GRID blocks resident by construction
__device__ __forceinline__ void gbar(int p) {
    __threadfence();
    __syncthreads();
    if (threadIdx.x == 0) {
        atomicAdd(&g_bar[p], 1);
        while (ld_cg(&g_bar[p]) < GRID) __nanosleep(32);
    }
    __syncthreads();
}

// ---------------- the single persistent kernel ----------------
__global__ void __launch_bounds__(NTHR) k_fused(
        const float* __restrict__ inp, const void* __restrict__ dep,
        const void* __restrict__ ei,   const float* __restrict__ weight,
        const float* __restrict__ wcomp, const float* __restrict__ sw,
        const float* __restrict__ bias, float* __restrict__ out) {
    extern __shared__ float sm[];
    float4* sW4   = (float4*)sm;                  // 4096 float4 = 64 KB (full W)
    float*  xs    = sm + 16384;                   // 64 rows * stride 132 (16B aligned)
    int*    s_src = (int*)(xs + TROWS*XS_STRIDE);
    int*    s_tgt = s_src + TROWS;
    float*  s_inv = (float*)(s_tgt + TROWS);
    int*    s_misc= (int*)(s_inv + TROWS);        // [0]=tile ticket / sniff flag

    const int bid = blockIdx.x, tid = threadIdx.x;
    const int gtid = bid*NTHR + tid, G = GRID*NTHR;

    // ---- phase 0: zero scratch & output, reset ticket, sniff index width ----
    {
        const int4 z4 = make_int4(0,0,0,0);
        for (int k = gtid; k < NN*RR/4; k += G) ((int4*)g_comb)[k] = z4;
        const float4 f4 = make_float4(0.f,0.f,0.f,0.f);
        for (int k = gtid; k < NN*DD/4; k += G) ((float4*)out)[k] = f4;
        if (gtid < RR*8) g_cnt8[gtid] = 0;
        if (gtid == 0) g_ticket = 0u;
        if (bid == 0) {                            // int64-vs-int32 sniff on edge_index
            if (tid == 0) s_misc[0] = 0;
            __syncthreads();
            int any = 0;
            const unsigned* eu = (const unsigned*)ei;
            for (int k = tid; k < 2048; k += NTHR)
                if (eu[2*k + 1] != 0u) any = 1;
            if (any) atomicOr(s_misc, 1);
            __syncthreads();
            if (tid == 0) g_is64 = (s_misc[0] == 0) ? 1 : 0;
        }
    }
    gbar(0);

    // ---- phase 1: decode indices, bucket counts, banked ranks ----
    if (gtid < NE) {
        const int e = gtid;
        int rel, s, t;
        if (g_is64) {
            rel = (int)((const long long*)dep)[e];
            s   = (int)((const long long*)ei)[e];
            t   = (int)((const long long*)ei)[NE + e];
        } else {
            rel = ((const int*)dep)[e];
            s   = ((const int*)ei)[e];
            t   = ((const int*)ei)[NE + e];
        }
        g_rel[e] = rel; g_src[e] = s; g_tgt[e] = t;
        atomicAdd(&g_comb[t*RR + rel], 1);
        const int bank = bid & 7;
        const int rk = atomicAdd(&g_cnt8[rel*8 + bank], 1);
        g_rank[e] = (bank << 16) | rk;
    }
    gbar(1);

    // ---- phase 2: basis expansion + W^T + scan + tile list ----
    if (bid < DD) {                                // full_weight[:, i=bid, :]
        const int i = bid, j = tid & 127, rh = tid >> 7;   // rh in 0..3 -> 16 r's
        for (int k = tid; k < RR*BB; k += NTHR) sm[k] = wcomp[k];
        float wr[BB];
        #pragma unroll
        for (int b = 0; b < BB; b++) wr[b] = weight[(b*DD + i)*DD + j];
        __syncthreads();
        #pragma unroll 4
        for (int r = rh*16; r < rh*16 + 16; r++) {
            float a = 0.f;
            #pragma unroll
            for (int b = 0; b < BB; b++) a += sm[r*BB + b] * wr[b];
            g_fullW[((size_t)r*DD + i)*DD + j] = a;
        }
    } else if (bid < DD + 16) {                    // self_weight transpose, 8 rows/block
        const int i = tid & 127, q = tid >> 7;     // q in 0..3
        const int j0 = (bid - DD)*8;
        g_swT[i*DD + j0 + q]     = sw[(j0 + q)*DD + i];
        g_swT[i*DD + j0 + q + 4] = sw[(j0 + q + 4)*DD + i];
    } else if (bid == DD + 16) {                   // scan 512 bank counters + tile list
        if (tid < 32) {
            int vals[16], local = 0;
            #pragma unroll
            for (int k = 0; k < 16; k++) {
                int c = g_cnt8[tid*16 + k];
                vals[k] = local; local += c;
            }
            int x = local;
            #pragma unroll
            for (int d = 1; d < 32; d <<= 1) {
                int y = __shfl_up_sync(0xffffffffu, x, d);
                if ((tid & 31) >= d) x += y;
            }
            const int excl = x - local;
            #pragma unroll
            for (int k = 0; k < 16; k++) g_off8[tid*16 + k] = excl + vals[k];
            __syncwarp();
            if (tid == 0) {
                int nt = 0;
                for (int r = 0; r < RR; r++) {
                    const int start = g_off8[r*8];
                    const int end = (r == RR-1) ? NE : g_off8[(r+1)*8];
                    const int cnt = end - start;
                    g_reloff[r] = start; g_relcnt[r] = cnt;
                    for (int c = 0; c*TROWS < cnt; c++) g_tiles[nt++] = (r << 8) | c;
                }
                g_ntiles = nt;
            }
        }
    }
    gbar(2);

    // ---- phase 3: atomic-free counting-sort scatter ----
    if (gtid < NE) {
        const int e = gtid;
        const int rel = g_rel[e], rb = g_rank[e];
        g_sorted[g_off8[rel*8 + (rb >> 16)] + (rb & 0xffff)] = e;
    }
    gbar(3);

    // ---- phase 4: work-stealing tiled matvec (edge tiles first, self last) ----
    const int ntiles = g_ntiles;
    const int ntotal = ntiles + NN/TROWS;          // + 128 self tiles
    const int row = tid & 63;                      // tile row
    const int jo  = tid >> 6;                      // 0..7: 16 output cols each
    const float4* last_w = (const float4*)0;

    for (;;) {
        __syncthreads();                           // protect smem + s_misc reuse
        if (tid == 0) s_misc[0] = (int)atomicAdd(&g_ticket, 1u);
        __syncthreads();
        const int t = s_misc[0];
        if (t >= ntotal) break;

        const bool is_self = (t >= ntiles);
        int rel = 0, base, cnt, off = 0;
        if (is_self) { base = (t - ntiles)*TROWS; cnt = NN; }
        else {
            const int tt = g_tiles[t];
            rel = tt >> 8; base = (tt & 255)*TROWS;
            cnt = g_relcnt[rel]; off = g_reloff[rel];
        }

        if (tid < TROWS) {                         // per-row metadata
            if (is_self) {
                s_src[tid] = base + tid; s_tgt[tid] = base + tid; s_inv[tid] = 1.f;
            } else {
                const int le = base + tid;
                const bool v = le < cnt;
                const int e = g_sorted[off + (v ? le : base)];
                const int sN = g_src[e], tN = g_tgt[e];
                s_src[tid] = sN; s_tgt[tid] = tN;
                s_inv[tid] = v ? 1.0f/(float)g_comb[tN*RR + rel] : 0.f;
            }
        }
        // stage W (128x128) into smem, skipped when unchanged from last tile
        const float4* wsrc = is_self ? (const float4*)g_swT
                                     : (const float4*)g_fullW + (size_t)rel*4096;
        if (wsrc != last_w) {
            #pragma unroll 8
            for (int k = tid; k < 4096; k += NTHR) sW4[k] = wsrc[k];
            last_w = wsrc;
        }
        __syncthreads();

        // vectorized coalesced gather of the 64 x-rows (32 lanes x float4 per row)
        {
            const int c4 = tid & 31;
            #pragma unroll
            for (int r2 = tid >> 5; r2 < TROWS; r2 += 16)
                ((float4*)(xs + r2*XS_STRIDE))[c4] =
                    ((const float4*)(inp + (size_t)s_src[r2]*DD))[c4];
        }
        __syncthreads();

        // warps whose 32 rows are all past cnt skip compute entirely
        if (is_self || (base + (row & 32)) < cnt) {
            u64 acc[8];
            #pragma unroll
            for (int a = 0; a < 8; a++) acc[a] = 0ull;
            const float4* xr4 = (const float4*)(xs + row*XS_STRIDE);
            const ulonglong2* W8 = (const ulonglong2*)sW4;

            #pragma unroll 4
            for (int i4 = 0; i4 < 32; i4++) {
                const float4 xv = xr4[i4];
                const float xf[4] = {xv.x, xv.y, xv.z, xv.w};
                #pragma unroll
                for (int s = 0; s < 4; s++) {
                    const u64 xx = pack2(xf[s]);
                    const ulonglong2* wr = W8 + (i4*4 + s)*32 + jo*4;
                    const ulonglong2 w0 = wr[0], w1 = wr[1], w2 = wr[2], w3 = wr[3];
                    ffma2(acc[0], xx, w0.x); ffma2(acc[1], xx, w0.y);
                    ffma2(acc[2], xx, w1.x); ffma2(acc[3], xx, w1.y);
                    ffma2(acc[4], xx, w2.x); ffma2(acc[5], xx, w2.y);
                    ffma2(acc[6], xx, w3.x); ffma2(acc[7], xx, w3.y);
                }
            }
            if (is_self || base + row < cnt) {
                const float inv = s_inv[row];
                float* op = out + (size_t)s_tgt[row]*DD + jo*16;
                #pragma unroll
                for (int q = 0; q < 4; q++) {
                    const float2 a = unpack2(acc[2*q]);
                    const float2 b = unpack2(acc[2*q + 1]);
                    float v0 = a.x*inv, v1 = a.y*inv, v2 = b.x*inv, v3 = b.y*inv;
                    if (is_self) {
                        const float4 bb = ((const float4*)bias)[jo*4 + q];
                        v0 += bb.x; v1 += bb.y; v2 += bb.z; v3 += bb.w;
                    }
                    red4(op + 4*q, v0, v1, v2, v3);
                }
            }
        }
    }

    // ---- epilogue: last-arriving block resets barrier counters for replay ----
    __threadfence();
    __syncthreads();
    if (tid == 0) {
        const int a = atomicAdd(&g_bar[7], 1);
        if (a == GRID - 1) {
            #pragma unroll
            for (int p = 0; p < 8; p++) g_bar[p] = 0;
            __threadfence();
        }
    }
}

// ---------------- launch ----------------
extern "C" void kernel_launch(void* const* d_in, const int* in_sizes, int n_in,
                              void* d_out, int out_size) {
    const float* inp    = (const float*)d_in[0];
    const void*  dep    = d_in[1];
    const void*  ei     = d_in[2];
    const float* weight = (const float*)d_in[3];
    const float* wcomp  = (const float*)d_in[4];
    const float* sw     = (const float*)d_in[5];
    const float* bias   = (const float*)d_in[6];
    float* out = (float*)d_out;

    // 64KB W + 64*132*4 xs + meta
    const int SMEM = 16384*4 + TROWS*XS_STRIDE*4 + TROWS*4*3 + 64;
    cudaFuncSetAttribute(k_fused, cudaFuncAttributeMaxDynamicSharedMemorySize, SMEM);

    k_fused<<<GRID, NTHR, SMEM>>>(inp, dep, ei, weight, wcomp, sw, bias, out);
}

// round 5
// speedup vs baseline: 1.7761x; 1.0567x over previous
#include <cuda_runtime.h>

#define NN 8192
#define NE 16384
#define DD 128
#define RR 64
#define BB 16
#define GRID 148
#define NTHR 512
#define TROWS 64
#define XT_STRIDE 68        // xsT row stride in words (64 rows + 4 pad, 16B-aligned)

typedef unsigned long long u64;

// ---------------- device scratch (no allocations allowed) ----------------
__device__ __align__(16) float g_fullW[RR*DD*DD];   // 4 MB expanded basis
__device__ __align__(16) float g_swT[DD*DD];        // self_weight transposed
__device__ int g_comb[NN*RR];                       // (tgt,rel) bucket counts
__device__ int g_cnt8[RR*8];                        // banked relation counters
__device__ int g_off8[RR*8];                        // scanned bank offsets
__device__ int g_relcnt[RR], g_reloff[RR];
__device__ int g_src[NE], g_tgt[NE], g_rel[NE], g_rank[NE];
__device__ int g_sorted[NE];
__device__ int g_tiles[2048], g_ntiles;
__device__ int g_is64;
__device__ int g_bar[8];
__device__ int g_sdone;
__device__ unsigned g_ticket;

// ---------------- helpers ----------------
__device__ __forceinline__ u64 pack2(float x) {
    u64 r; asm("mov.b64 %0, {%1, %1};" : "=l"(r) : "f"(x)); return r;
}
__device__ __forceinline__ void ffma2(u64& d, u64 a, u64 b) {
    asm("fma.rn.f32x2 %0, %1, %2, %0;" : "+l"(d) : "l"(a), "l"(b));
}
__device__ __forceinline__ float2 unpack2(u64 v) {
    float2 f; asm("mov.b64 {%0, %1}, %2;" : "=f"(f.x), "=f"(f.y) : "l"(v)); return f;
}
__device__ __forceinline__ void red2(float* p, float a, float b) {
    asm volatile("red.global.add.v2.f32 [%0], {%1,%2};"
                 :: "l"(p), "f"(a), "f"(b) : "memory");
}
__device__ __forceinline__ int ld_cg(const int* p) {
    int v; asm volatile("ld.global.cg.b32 %0, [%1];" : "=r"(v) : "l"(p) : "memory"); return v;
}
__device__ __forceinline__ void gbar(int p) {
    __threadfence();
    __syncthreads();
    if (threadIdx.x == 0) {
        atomicAdd(&g_bar[p], 1);
        while (ld_cg(&g_bar[p]) < GRID) __nanosleep(32);
    }
    __syncthreads();
}

// ---------------- the single persistent kernel ----------------
__global__ void __launch_bounds__(NTHR, 1) k_fused(
        const float* __restrict__ inp, const void* __restrict__ dep,
        const void* __restrict__ ei,   const float* __restrict__ weight,
        const float* __restrict__ wcomp, const float* __restrict__ sw,
        const float* __restrict__ bias, float* __restrict__ out) {
    extern __shared__ float sm[];
    float* sW    = sm;                    // (128+1)*128 = 16512 floats (pad k-row)
    float* xsT   = sm + 16512;            // (128+1)*68  =  8772 floats (transposed x)
    int*   s_src = (int*)(xsT + 8772);
    float* s_inv = (float*)(s_src + TROWS);
    int*   s_tgt = (int*)(s_inv + TROWS);
    int*   s_misc= (int*)(s_tgt + TROWS);

    const int bid = blockIdx.x, tid = threadIdx.x;
    const int gtid = bid*NTHR + tid, G = GRID*NTHR;
    const int wid = tid >> 5, lane = tid & 31;

    // ---- phase 0: zero scratch & output, reset counters, sniff index width ----
    {
        const int4 z4 = make_int4(0,0,0,0);
        for (int k = gtid; k < NN*RR/4; k += G) ((int4*)g_comb)[k] = z4;
        const float4 f4 = make_float4(0.f,0.f,0.f,0.f);
        for (int k = gtid; k < NN*DD/4; k += G) ((float4*)out)[k] = f4;
        if (gtid < RR*8) g_cnt8[gtid] = 0;
        if (gtid == 0) { g_ticket = 0u; g_sdone = 0; }
        if (bid == 0) {                              // int64-vs-int32 sniff
            if (tid == 0) s_misc[0] = 0;
            __syncthreads();
            int any = 0;
            const unsigned* eu = (const unsigned*)ei;
            for (int k = tid; k < 8192; k += NTHR)
                if (eu[2*k + 1] != 0u) any = 1;
            if (any) atomicOr(s_misc, 1);
            __syncthreads();
            if (tid == 0) g_is64 = (s_misc[0] == 0) ? 1 : 0;
        }
    }
    gbar(0);

    // ---- phase 1: decode (blocks 0..31) || basis (32..143) || swT (144..147) ----
    if (bid < 32) {
        const int e = gtid;                          // 32*512 = 16384 = NE
        int rel, s, t;
        if (g_is64) {
            rel = (int)((const long long*)dep)[e];
            s   = (int)((const long long*)ei)[e];
            t   = (int)((const long long*)ei)[NE + e];
        } else {
            rel = ((const int*)dep)[e];
            s   = ((const int*)ei)[e];
            t   = ((const int*)ei)[NE + e];
        }
        g_rel[e] = rel; g_src[e] = s; g_tgt[e] = t;
        atomicAdd(&g_comb[t*RR + rel], 1);
        const int bank = bid & 7;
        const int rk = atomicAdd(&g_cnt8[rel*8 + bank], 1);
        g_rank[e] = (bank << 16) | rk;
    } else if (bid < 144) {                          // basis: 112 blocks, 128 i's
        const int j = tid & 127, rh = tid >> 7;      // rh in 0..3 -> 16 r's each
        for (int k = tid; k < RR*BB; k += NTHR) sm[k] = wcomp[k];
        __syncthreads();
        const int npass = (bid - 32 < 16) ? 2 : 1;
        for (int ps = 0; ps < npass; ps++) {
            const int i = (bid - 32) + ps*112;
            float wr[BB];
            #pragma unroll
            for (int b = 0; b < BB; b++) wr[b] = weight[(b*DD + i)*DD + j];
            #pragma unroll 4
            for (int r = rh*16; r < rh*16 + 16; r++) {
                float a = 0.f;
                #pragma unroll
                for (int b = 0; b < BB; b++) a += sm[r*BB + b] * wr[b];
                g_fullW[((size_t)r*DD + i)*DD + j] = a;
            }
        }
    } else {                                         // swT: 4 blocks x 32 j-rows
        const int i = tid & 127, q = tid >> 7;
        #pragma unroll
        for (int jj = 0; jj < 8; jj++) {
            const int j = (bid - 144)*32 + q*8 + jj;
            g_swT[i*DD + j] = sw[j*DD + i];
        }
    }
    gbar(1);

    // ---- phase 2: scan bank counters + build tile list (block 0) ----
    if (bid == 0 && tid < 32) {
        int vals[16], local = 0;
        #pragma unroll
        for (int k = 0; k < 16; k++) {
            int c = g_cnt8[tid*16 + k];
            vals[k] = local; local += c;
        }
        int x = local;
        #pragma unroll
        for (int d = 1; d < 32; d <<= 1) {
            int y = __shfl_up_sync(0xffffffffu, x, d);
            if (lane >= d) x += y;
        }
        const int excl = x - local;
        #pragma unroll
        for (int k = 0; k < 16; k++) g_off8[tid*16 + k] = excl + vals[k];
        __syncwarp();
        if (tid == 0) {
            int nt = 0;
            for (int r = 0; r < RR; r++) {
                const int start = g_off8[r*8];
                const int end = (r == RR-1) ? NE : g_off8[(r+1)*8];
                const int cnt = end - start;
                g_reloff[r] = start; g_relcnt[r] = cnt;
                for (int c = 0; c*TROWS < cnt; c++) g_tiles[nt++] = (r << 8) | c;
            }
            g_ntiles = nt;
        }
    }
    gbar(2);

    // ---- phase 3 (overlapped): blocks 0..31 scatter, then join compute ----
    if (bid < 32) {
        const int e = gtid;
        const int rel = g_rel[e], rb = g_rank[e];
        g_sorted[g_off8[rel*8 + (rb >> 16)] + (rb & 0xffff)] = e;
        __threadfence();
        __syncthreads();
        if (tid == 0) atomicAdd(&g_sdone, 1);
    }

    // ---- phase 4: ticketed tiles — self (0..127) first, then edges ----
    const int ntiles = g_ntiles;
    const int ntotal = 128 + ntiles;
    // compute mapping: thread = 8 rows x 2 cols
    const int a  = lane & 7;                   // rows 4a..4a+3 and 4a+32..4a+35
    const int c0 = wid*8 + (lane >> 3)*2;      // 2 output cols
    const float* last_w = (const float*)0;
    bool edges_ok = false;

    for (;;) {
        __syncthreads();                       // previous tile fully consumed
        if (tid == 0) s_misc[0] = (int)atomicAdd(&g_ticket, 1u);
        __syncthreads();
        const int t = s_misc[0];
        if (t >= ntotal) break;

        const bool is_self = (t < 128);
        int rel = 0, base, cnt, off = 0;
        if (is_self) { base = t*TROWS; cnt = NN; }
        else {
            if (!edges_ok) {                   // gate on scatter completion
                if (tid == 0) while (ld_cg(&g_sdone) < 32) __nanosleep(64);
                __syncthreads();
                edges_ok = true;
            }
            const int tt = g_tiles[t - 128];
            rel = tt >> 8; base = (tt & 255)*TROWS;
            cnt = g_relcnt[rel]; off = g_reloff[rel];
        }

        if (tid < TROWS) {                     // per-row metadata
            if (is_self) {
                s_src[tid] = base + tid; s_tgt[tid] = base + tid; s_inv[tid] = 1.f;
            } else {
                const int le = base + tid;
                const bool v = le < cnt;
                const int e = g_sorted[off + (v ? le : base)];
                const int sN = g_src[e], tN = g_tgt[e];
                s_src[tid] = sN; s_tgt[tid] = tN;
                s_inv[tid] = v ? 1.0f/(float)g_comb[tN*RR + rel] : 0.f;
            }
        }
        // stage W [128k x 128c] into smem (skip if unchanged)
        const float* wsrc = is_self ? g_swT : g_fullW + (size_t)rel*DD*DD;
        if (wsrc != last_w) {
            #pragma unroll 8
            for (int k = tid; k < 4096; k += NTHR)
                ((float4*)sW)[k] = ((const float4*)wsrc)[k];
            last_w = wsrc;
        }
        __syncthreads();

        // gather x transposed: warp = (row-half, k-quarter-group), lane = row
        {
            const int half = wid & 1, kq = wid >> 1;
            const int r = 32*half + lane;
            const float4* ip = (const float4*)(inp + (size_t)s_src[r]*DD);
            #pragma unroll
            for (int p = 0; p < 4; p++) {
                const int k4 = kq + 8*p;
                const float4 v = ip[k4];
                xsT[(4*k4 + 0)*XT_STRIDE + r] = v.x;
                xsT[(4*k4 + 1)*XT_STRIDE + r] = v.y;
                xsT[(4*k4 + 2)*XT_STRIDE + r] = v.z;
                xsT[(4*k4 + 3)*XT_STRIDE + r] = v.w;
            }
        }
        __syncthreads();

        // fma-dense inner loop with next-k register prefetch
        u64 acc[8];
        #pragma unroll
        for (int q = 0; q < 8; q++) acc[q] = 0ull;
        {
            const float* xt0 = xsT + 4*a;
            const float* xt1 = xsT + 4*a + 32;
            const float* wp  = sW + c0;
            ulonglong2 x0 = *(const ulonglong2*)xt0;
            ulonglong2 x1 = *(const ulonglong2*)xt1;
            float2 wv = *(const float2*)wp;
            #pragma unroll 4
            for (int k = 0; k < DD; k++) {
                const ulonglong2 nx0 = *(const ulonglong2*)(xt0 + (k+1)*XT_STRIDE);
                const ulonglong2 nx1 = *(const ulonglong2*)(xt1 + (k+1)*XT_STRIDE);
                const float2     nwv = *(const float2*)(wp + (k+1)*DD);
                const u64 w0 = pack2(wv.x), w1 = pack2(wv.y);
                ffma2(acc[0], x0.x, w0); ffma2(acc[1], x0.x, w1);
                ffma2(acc[2], x0.y, w0); ffma2(acc[3], x0.y, w1);
                ffma2(acc[4], x1.x, w0); ffma2(acc[5], x1.x, w1);
                ffma2(acc[6], x1.y, w0); ffma2(acc[7], x1.y, w1);
                x0 = nx0; x1 = nx1; wv = nwv;
            }
        }

        // epilogue: 4 row-pairs -> red.v2 per valid row
        float b0 = 0.f, b1 = 0.f;
        if (is_self) { b0 = __ldg(bias + c0); b1 = __ldg(bias + c0 + 1); }
        #pragma unroll
        for (int p = 0; p < 4; p++) {
            const int r = (p < 2) ? (4*a + 2*p) : (4*a + 32 + 2*(p-2));
            const float2 ca = unpack2(acc[2*p]);       // col c0,   rows (r, r+1)
            const float2 cb = unpack2(acc[2*p + 1]);   // col c0+1
            const float i0 = s_inv[r], i1 = s_inv[r+1];
            if (i0 != 0.f)
                red2(out + (size_t)s_tgt[r]*DD + c0,   ca.x*i0 + b0, cb.x*i0 + b1);
            if (i1 != 0.f)
                red2(out + (size_t)s_tgt[r+1]*DD + c0, ca.y*i1 + b0, cb.y*i1 + b1);
        }
    }

    // ---- epilogue: last block resets barriers/flags for graph replay ----
    __threadfence();
    __syncthreads();
    if (tid == 0) {
        const int done = atomicAdd(&g_bar[7], 1);
        if (done == GRID - 1) {
            #pragma unroll
            for (int p = 0; p < 8; p++) g_bar[p] = 0;
            __threadfence();
        }
    }
}

// ---------------- launch ----------------
extern "C" void kernel_launch(void* const* d_in, const int* in_sizes, int n_in,
                              void* d_out, int out_size) {
    const float* inp    = (const float*)d_in[0];
    const void*  dep    = d_in[1];
    const void*  ei     = d_in[2];
    const float* weight = (const float*)d_in[3];
    const float* wcomp  = (const float*)d_in[4];
    const float* sw     = (const float*)d_in[5];
    const float* bias   = (const float*)d_in[6];
    float* out = (float*)d_out;

    const int SMEM = (16512 + 8772 + TROWS*3 + 8) * 4;   // ~101.9 KB
    cudaFuncSetAttribute(k_fused, cudaFuncAttributeMaxDynamicSharedMemorySize, SMEM);

    k_fused<<<GRID, NTHR, SMEM>>>(inp, dep, ei, weight, wcomp, sw, bias, out);
}

// round 6
// speedup vs baseline: 2.0973x; 1.1809x over previous
#include <cuda_runtime.h>

#define NN 8192
#define NE 16384
#define DD 128
#define RR 64
#define BB 16
#define GRID 148
#define NTHR 512
#define TROWS 64
#define XT_STRIDE 68        // xsT k-row stride in words (64 rows + 4 pad)

typedef unsigned long long u64;

// ---------------- device scratch (no allocations allowed) ----------------
__device__ __align__(16) float g_fullW[RR*DD*DD];   // 4 MB expanded basis
__device__ __align__(16) float g_swT[DD*DD];        // self_weight transposed
__device__ int g_comb[NN*RR];                       // (tgt,rel) bucket counts
__device__ int g_cnt8[RR*8];                        // banked relation counters
__device__ int g_off8[RR*8];                        // scanned bank offsets
__device__ int g_relcnt[RR], g_reloff[RR];
__device__ int g_src[NE], g_tgt[NE], g_rel[NE], g_rank[NE];
__device__ int g_sorted[NE];
__device__ int g_tiles[2048], g_ntiles;
__device__ int g_is64;
__device__ int g_bar[8];
__device__ int g_sdone;
__device__ unsigned g_ticket;

// ---------------- helpers ----------------
__device__ __forceinline__ u64 pack2(float x) {
    u64 r; asm("mov.b64 %0, {%1, %1};" : "=l"(r) : "f"(x)); return r;
}
__device__ __forceinline__ void ffma2(u64& d, u64 a, u64 b) {
    asm("fma.rn.f32x2 %0, %1, %2, %0;" : "+l"(d) : "l"(a), "l"(b));
}
__device__ __forceinline__ float2 unpack2(u64 v) {
    float2 f; asm("mov.b64 {%0, %1}, %2;" : "=f"(f.x), "=f"(f.y) : "l"(v)); return f;
}
__device__ __forceinline__ void red4(float* p, float a, float b, float c, float d) {
    asm volatile("red.global.add.v4.f32 [%0], {%1,%2,%3,%4};"
                 :: "l"(p), "f"(a), "f"(b), "f"(c), "f"(d) : "memory");
}
__device__ __forceinline__ int ld_cg(const int* p) {
    int v; asm volatile("ld.global.cg.b32 %0, [%1];" : "=r"(v) : "l"(p) : "memory"); return v;
}
__device__ __forceinline__ void gbar(int p) {
    __threadfence();
    __syncthreads();
    if (threadIdx.x == 0) {
        atomicAdd(&g_bar[p], 1);
        while (ld_cg(&g_bar[p]) < GRID) __nanosleep(32);
    }
    __syncthreads();
}

// ---------------- the single persistent kernel ----------------
__global__ void __launch_bounds__(NTHR, 1) k_fused(
        const float* __restrict__ inp, const void* __restrict__ dep,
        const void* __restrict__ ei,   const float* __restrict__ weight,
        const float* __restrict__ wcomp, const float* __restrict__ sw,
        const float* __restrict__ bias, float* __restrict__ out) {
    extern __shared__ float sm[];
    float* sW    = sm;                    // (128+1)*128 = 16512 floats (pad k-row)
    float* xsT   = sm + 16512;            // (128+1)*68  =  8772 floats (transposed x)
    int*   s_src = (int*)(xsT + 8772);
    float* s_inv = (float*)(s_src + TROWS);
    int*   s_tgt = (int*)(s_inv + TROWS);
    int*   s_misc= (int*)(s_tgt + TROWS);

    const int bid = blockIdx.x, tid = threadIdx.x;
    const int gtid = bid*NTHR + tid, G = GRID*NTHR;
    const int wid = tid >> 5, lane = tid & 31;

    // ---- phase 0: zero scratch & output, reset counters, sniff index width ----
    {
        const int4 z4 = make_int4(0,0,0,0);
        for (int k = gtid; k < NN*RR/4; k += G) ((int4*)g_comb)[k] = z4;
        const float4 f4 = make_float4(0.f,0.f,0.f,0.f);
        for (int k = gtid; k < NN*DD/4; k += G) ((float4*)out)[k] = f4;
        if (gtid < RR*8) g_cnt8[gtid] = 0;
        if (gtid == 0) { g_ticket = 0u; g_sdone = 0; }
        if (bid == 0) {                              // int64-vs-int32 sniff
            if (tid == 0) s_misc[0] = 0;
            __syncthreads();
            int any = 0;
            const unsigned* eu = (const unsigned*)ei;
            for (int k = tid; k < 8192; k += NTHR)
                if (eu[2*k + 1] != 0u) any = 1;
            if (any) atomicOr(s_misc, 1);
            __syncthreads();
            if (tid == 0) g_is64 = (s_misc[0] == 0) ? 1 : 0;
        }
    }
    gbar(0);

    // ---- phase 1: decode (blocks 0..31) || basis (32..143) || swT (144..147) ----
    if (bid < 32) {
        const int e = gtid;                          // 32*512 = 16384 = NE
        int rel, s, t;
        if (g_is64) {
            rel = (int)((const long long*)dep)[e];
            s   = (int)((const long long*)ei)[e];
            t   = (int)((const long long*)ei)[NE + e];
        } else {
            rel = ((const int*)dep)[e];
            s   = ((const int*)ei)[e];
            t   = ((const int*)ei)[NE + e];
        }
        g_rel[e] = rel; g_src[e] = s; g_tgt[e] = t;
        atomicAdd(&g_comb[t*RR + rel], 1);
        const int bank = bid & 7;
        const int rk = atomicAdd(&g_cnt8[rel*8 + bank], 1);
        g_rank[e] = (bank << 16) | rk;
    } else if (bid < 144) {                          // basis: 112 blocks, 128 i's
        const int j = tid & 127, rh = tid >> 7;      // rh in 0..3 -> 16 r's each
        for (int k = tid; k < RR*BB; k += NTHR) sm[k] = wcomp[k];
        __syncthreads();
        const int npass = (bid - 32 < 16) ? 2 : 1;
        for (int ps = 0; ps < npass; ps++) {
            const int i = (bid - 32) + ps*112;
            float wr[BB];
            #pragma unroll
            for (int b = 0; b < BB; b++) wr[b] = weight[(b*DD + i)*DD + j];
            #pragma unroll 4
            for (int r = rh*16; r < rh*16 + 16; r++) {
                float a = 0.f;
                #pragma unroll
                for (int b = 0; b < BB; b++) a += sm[r*BB + b] * wr[b];
                g_fullW[((size_t)r*DD + i)*DD + j] = a;
            }
        }
    } else {                                         // swT: 4 blocks x 32 j-rows
        const int i = tid & 127, q = tid >> 7;
        #pragma unroll
        for (int jj = 0; jj < 8; jj++) {
            const int j = (bid - 144)*32 + q*8 + jj;
            g_swT[i*DD + j] = sw[j*DD + i];
        }
    }
    gbar(1);

    // ---- phase 2: scan bank counters + build tile list (block 0) ----
    if (bid == 0 && tid < 32) {
        int vals[16], local = 0;
        #pragma unroll
        for (int k = 0; k < 16; k++) {
            int c = g_cnt8[tid*16 + k];
            vals[k] = local; local += c;
        }
        int x = local;
        #pragma unroll
        for (int d = 1; d < 32; d <<= 1) {
            int y = __shfl_up_sync(0xffffffffu, x, d);
            if (lane >= d) x += y;
        }
        const int excl = x - local;
        #pragma unroll
        for (int k = 0; k < 16; k++) g_off8[tid*16 + k] = excl + vals[k];
        __syncwarp();
        if (tid == 0) {
            int nt = 0;
            for (int r = 0; r < RR; r++) {
                const int start = g_off8[r*8];
                const int end = (r == RR-1) ? NE : g_off8[(r+1)*8];
                const int cnt = end - start;
                g_reloff[r] = start; g_relcnt[r] = cnt;
                for (int c = 0; c*TROWS < cnt; c++) g_tiles[nt++] = (r << 8) | c;
            }
            g_ntiles = nt;
        }
    }
    gbar(2);

    // ---- phase 3 (overlapped): blocks 0..31 scatter, then join compute ----
    if (bid < 32) {
        const int e = gtid;
        const int rel = g_rel[e], rb = g_rank[e];
        g_sorted[g_off8[rel*8 + (rb >> 16)] + (rb & 0xffff)] = e;
        __threadfence();
        __syncthreads();
        if (tid == 0) atomicAdd(&g_sdone, 1);
    }

    // ---- phase 4: ticketed tiles — self (0..127) first, then edges ----
    const int ntiles = g_ntiles;
    const int ntotal = 128 + ntiles;
    // compute mapping: 4 rows x 4 cols per thread, warp = 2 ty x 16 tx
    const int tyP = wid & 7, txH = wid >> 3;
    const int ty = 2*tyP + (lane >> 4);        // 0..15 -> rows 4ty..4ty+3
    const int tx = txH*16 + (lane & 15);       // 0..31 -> cols 4tx..4tx+3
    const float* last_w = (const float*)0;
    bool edges_ok = false;

    for (;;) {
        __syncthreads();                       // previous tile fully consumed
        if (tid == 0) s_misc[0] = (int)atomicAdd(&g_ticket, 1u);
        __syncthreads();
        const int t = s_misc[0];
        if (t >= ntotal) break;

        const bool is_self = (t < 128);
        int rel = 0, base, cnt, off = 0;
        if (is_self) { base = t*TROWS; cnt = NN; }
        else {
            if (!edges_ok) {                   // gate on scatter completion
                if (tid == 0) while (ld_cg(&g_sdone) < 32) __nanosleep(64);
                __syncthreads();
                edges_ok = true;
            }
            const int tt = g_tiles[t - 128];
            rel = tt >> 8; base = (tt & 255)*TROWS;
            cnt = g_relcnt[rel]; off = g_reloff[rel];
        }

        if (tid < TROWS) {                     // per-row metadata
            if (is_self) {
                s_src[tid] = base + tid; s_tgt[tid] = base + tid; s_inv[tid] = 1.f;
            } else {
                const int le = base + tid;
                const bool v = le < cnt;
                const int e = g_sorted[off + (v ? le : base)];
                const int sN = g_src[e], tN = g_tgt[e];
                s_src[tid] = sN; s_tgt[tid] = tN;
                s_inv[tid] = v ? 1.0f/(float)g_comb[tN*RR + rel] : 0.f;
            }
        }
        // stage W [128k x 128c] into smem (skip if unchanged from last tile)
        const float* wsrc = is_self ? g_swT : g_fullW + (size_t)rel*DD*DD;
        if (wsrc != last_w) {
            #pragma unroll 8
            for (int k = tid; k < 4096; k += NTHR)
                ((float4*)sW)[k] = ((const float4*)wsrc)[k];
            last_w = wsrc;
        }
        __syncthreads();

        // gather x transposed: warp = (row-half, k-quarter-group), lane = row
        {
            const int half = wid & 1, kq = wid >> 1;
            const int r = 32*half + lane;
            const float4* ip = (const float4*)(inp + (size_t)s_src[r]*DD);
            #pragma unroll
            for (int p = 0; p < 4; p++) {
                const int k4 = kq + 8*p;
                const float4 v = ip[k4];
                xsT[(4*k4 + 0)*XT_STRIDE + r] = v.x;
                xsT[(4*k4 + 1)*XT_STRIDE + r] = v.y;
                xsT[(4*k4 + 2)*XT_STRIDE + r] = v.z;
                xsT[(4*k4 + 3)*XT_STRIDE + r] = v.w;
            }
        }
        __syncthreads();

        // warps whose 8 rows are all past cnt skip compute entirely
        if (is_self || base + tyP*8 < cnt) {
            u64 acc[8];                        // [row 0..3][colpair 0..1]
            #pragma unroll
            for (int q = 0; q < 8; q++) acc[q] = 0ull;

            const float* xp = xsT + 4*ty;
            const float* wp = sW + 4*tx;
            float4 xv = *(const float4*)xp;
            ulonglong2 wv = *(const ulonglong2*)wp;
            #pragma unroll 4
            for (int k = 0; k < DD; k++) {
                const float4     nxv = *(const float4*)(xp + (k+1)*XT_STRIDE);
                const ulonglong2 nwv = *(const ulonglong2*)(wp + (k+1)*DD);
                const u64 x0 = pack2(xv.x), x1 = pack2(xv.y);
                const u64 x2 = pack2(xv.z), x3 = pack2(xv.w);
                ffma2(acc[0], x0, wv.x); ffma2(acc[1], x0, wv.y);
                ffma2(acc[2], x1, wv.x); ffma2(acc[3], x1, wv.y);
                ffma2(acc[4], x2, wv.x); ffma2(acc[5], x2, wv.y);
                ffma2(acc[6], x3, wv.x); ffma2(acc[7], x3, wv.y);
                xv = nxv; wv = nwv;
            }

            // epilogue: one red.v4 per valid row (4 contiguous cols)
            float4 bb = make_float4(0.f, 0.f, 0.f, 0.f);
            if (is_self) bb = __ldg((const float4*)bias + tx);
            #pragma unroll
            for (int rr = 0; rr < 4; rr++) {
                const int r = 4*ty + rr;
                const float inv = s_inv[r];
                if (inv != 0.f) {
                    const float2 ca = unpack2(acc[2*rr]);
                    const float2 cb = unpack2(acc[2*rr + 1]);
                    red4(out + (size_t)s_tgt[r]*DD + 4*tx,
                         ca.x*inv + bb.x, ca.y*inv + bb.y,
                         cb.x*inv + bb.z, cb.y*inv + bb.w);
                }
            }
        }
    }

    // ---- epilogue: last block resets barriers/flags for graph replay ----
    __threadfence();
    __syncthreads();
    if (tid == 0) {
        const int done = atomicAdd(&g_bar[7], 1);
        if (done == GRID - 1) {
            #pragma unroll
            for (int p = 0; p < 8; p++) g_bar[p] = 0;
            __threadfence();
        }
    }
}

// ---------------- launch ----------------
extern "C" void kernel_launch(void* const* d_in, const int* in_sizes, int n_in,
                              void* d_out, int out_size) {
    const float* inp    = (const float*)d_in[0];
    const void*  dep    = d_in[1];
    const void*  ei     = d_in[2];
    const float* weight = (const float*)d_in[3];
    const float* wcomp  = (const float*)d_in[4];
    const float* sw     = (const float*)d_in[5];
    const float* bias   = (const float*)d_in[6];
    float* out = (float*)d_out;

    const int SMEM = (16512 + 8772 + TROWS*3 + 8) * 4;   // ~101.9 KB
    cudaFuncSetAttribute(k_fused, cudaFuncAttributeMaxDynamicSharedMemorySize, SMEM);

    k_fused<<<GRID, NTHR, SMEM>>>(inp, dep, ei, weight, wcomp, sw, bias, out);
}

// round 7
// speedup vs baseline: 2.5743x; 1.2274x over previous
#include <cuda_runtime.h>

#define NN 8192
#define NE 16384
#define DD 128
#define RR 64
#define BB 16
#define GRID 148
#define NTHR 512
#define TROWS 64
#define WS 132              // sW k-row stride in words (conflict-free transpose + aligned LDS.128)
#define XT_STRIDE 68        // xsT k-row stride in words (64 rows + 4 pad)

typedef unsigned long long u64;

// ---------------- device scratch (no allocations allowed) ----------------
__device__ __align__(16) float g_fullW[RR*DD*DD];   // 4 MB expanded basis
__device__ int g_comb[NN*RR];                       // (tgt,rel) bucket counts
__device__ int g_cnt8[RR*8];                        // banked relation counters
__device__ int g_off8[RR*8];                        // scanned bank offsets
__device__ int g_relcnt[RR], g_reloff[RR];
__device__ int g_src[NE], g_tgt[NE];
__device__ int g_sorted[NE];
__device__ int g_tiles[1024], g_ntiles;
__device__ int g_is64;
__device__ int g_bar[8];
__device__ int g_sdone, g_bdone, g_scan;
__device__ unsigned g_ticket;

// ---------------- helpers ----------------
__device__ __forceinline__ u64 pack2(float x) {
    u64 r; asm("mov.b64 %0, {%1, %1};" : "=l"(r) : "f"(x)); return r;
}
__device__ __forceinline__ void ffma2(u64& d, u64 a, u64 b) {
    asm("fma.rn.f32x2 %0, %1, %2, %0;" : "+l"(d) : "l"(a), "l"(b));
}
__device__ __forceinline__ float2 unpack2(u64 v) {
    float2 f; asm("mov.b64 {%0, %1}, %2;" : "=f"(f.x), "=f"(f.y) : "l"(v)); return f;
}
__device__ __forceinline__ void red4(float* p, float a, float b, float c, float d) {
    asm volatile("red.global.add.v4.f32 [%0], {%1,%2,%3,%4};"
                 :: "l"(p), "f"(a), "f"(b), "f"(c), "f"(d) : "memory");
}
__device__ __forceinline__ int ld_cg(const int* p) {
    int v; asm volatile("ld.global.cg.b32 %0, [%1];" : "=r"(v) : "l"(p) : "memory"); return v;
}

// ---------------- the single persistent kernel ----------------
__global__ void __launch_bounds__(NTHR, 1) k_fused(
        const float* __restrict__ inp, const void* __restrict__ dep,
        const void* __restrict__ ei,   const float* __restrict__ weight,
        const float* __restrict__ wcomp, const float* __restrict__ sw,
        const float* __restrict__ bias, float* __restrict__ out) {
    extern __shared__ float sm[];
    float* sW    = sm;                    // 129*132 = 17028 floats (pad k-row)
    float* xsT   = sm + 17028;            // 129*68  =  8772 floats (transposed x)
    int*   s_src = (int*)(xsT + 8772);
    float* s_inv = (float*)(s_src + TROWS);
    int*   s_tgt = (int*)(s_inv + TROWS);
    int*   s_misc= (int*)(s_tgt + TROWS);

    const int bid = blockIdx.x, tid = threadIdx.x;
    const int gtid = bid*NTHR + tid, G = GRID*NTHR;
    const int wid = tid >> 5, lane = tid & 31;

    // ---- phase 0: zero scratch & output, reset flags, quick index-width sniff ----
    {
        const int4 z4 = make_int4(0,0,0,0);
        for (int k = gtid; k < NN*RR/4; k += G) ((int4*)g_comb)[k] = z4;
        const float4 f4 = make_float4(0.f,0.f,0.f,0.f);
        for (int k = gtid; k < NN*DD/4; k += G) ((float4*)out)[k] = f4;
        if (gtid < RR*8) g_cnt8[gtid] = 0;
        if (gtid == 0) { g_ticket = 0u; g_sdone = 0; g_bdone = 0; g_scan = 0; }
        if (bid == 0 && wid == 0) {       // 32-sample sniff: int64 iff all hi words 0
            const unsigned* eu = (const unsigned*)ei;
            unsigned any = (eu[2*lane + 1] != 0u) ? 1u : 0u;
            any = __ballot_sync(0xffffffffu, any);
            if (lane == 0) g_is64 = (any == 0u) ? 1 : 0;
        }
    }
    // single global barrier (all GRID blocks resident by construction)
    __threadfence();
    __syncthreads();
    if (tid == 0) {
        atomicAdd(&g_bar[0], 1);
        while (ld_cg(&g_bar[0]) < GRID) __nanosleep(32);
    }
    __syncthreads();

    // ---- fork: blocks 0..31 = edge chain; blocks 32..147 = basis expansion ----
    if (bid < 32) {
        // decode 512 edges (kept in registers through the scan wait)
        const int e = bid*NTHR + tid;
        int rel, sN, tN;
        if (g_is64) {
            rel = (int)((const long long*)dep)[e];
            sN  = (int)((const long long*)ei)[e];
            tN  = (int)((const long long*)ei)[NE + e];
        } else {
            rel = ((const int*)dep)[e];
            sN  = ((const int*)ei)[e];
            tN  = ((const int*)ei)[NE + e];
        }
        g_src[e] = sN; g_tgt[e] = tN;
        atomicAdd(&g_comb[tN*RR + rel], 1);
        const int bank = bid & 7;
        const int rk = atomicAdd(&g_cnt8[rel*8 + bank], 1);

        // mini-barrier among the 32 decode blocks
        __threadfence();
        __syncthreads();
        if (tid == 0) atomicAdd(&g_bar[1], 1);

        if (bid == 0) {
            if (tid == 0) while (ld_cg(&g_bar[1]) < 32) __nanosleep(32);
            __syncthreads();
            if (tid < 32) {                       // parallel scan + tile list
                int vals[16], local = 0;
                #pragma unroll
                for (int k = 0; k < 16; k++) {
                    int c = g_cnt8[tid*16 + k];
                    vals[k] = local; local += c;
                }
                int x = local;
                #pragma unroll
                for (int d = 1; d < 32; d <<= 1) {
                    int y = __shfl_up_sync(0xffffffffu, x, d);
                    if (lane >= d) x += y;
                }
                const int excl = x - local;
                #pragma unroll
                for (int k = 0; k < 16; k++) g_off8[tid*16 + k] = excl + vals[k];
                const int r0 = 2*tid, r1 = 2*tid + 1;
                const int cnt0 = vals[8], cnt1 = local - vals[8];
                g_relcnt[r0] = cnt0; g_relcnt[r1] = cnt1;
                g_reloff[r0] = excl; g_reloff[r1] = excl + vals[8];
                const int nt0 = (cnt0 + TROWS-1)/TROWS, nt1 = (cnt1 + TROWS-1)/TROWS;
                const int ntl = nt0 + nt1;
                int ts = ntl;
                #pragma unroll
                for (int d = 1; d < 32; d <<= 1) {
                    int y = __shfl_up_sync(0xffffffffu, ts, d);
                    if (lane >= d) ts += y;
                }
                const int tbase = ts - ntl;
                for (int c = 0; c < nt0; c++) g_tiles[tbase + c] = (r0 << 8) | c;
                for (int c = 0; c < nt1; c++) g_tiles[tbase + nt0 + c] = (r1 << 8) | c;
                if (tid == 31) g_ntiles = ts;
            }
            __threadfence();
            __syncthreads();
            if (tid == 0) atomicExch(&g_scan, 1);
        } else {
            if (tid == 0) while (ld_cg(&g_scan) == 0) __nanosleep(32);
            __syncthreads();
        }
        // atomic-free counting-sort scatter from registers
        g_sorted[g_off8[rel*8 + bank] + rk] = e;
        __threadfence();
        __syncthreads();
        if (tid == 0) atomicAdd(&g_sdone, 1);
    } else {
        // basis expansion: block handles i = bid-32 (+116 for the first 12)
        const int j = tid & 127, rh = tid >> 7;          // rh 0..3 -> 16 r's each
        for (int k = tid; k < RR*BB; k += NTHR) sm[k] = wcomp[k];
        __syncthreads();
        const int i1 = bid - 32;
        const int npass = (i1 < 12) ? 2 : 1;
        for (int ps = 0; ps < npass; ps++) {
            const int i = i1 + ps*116;
            float wr[BB];
            #pragma unroll
            for (int b = 0; b < BB; b++) wr[b] = weight[(b*DD + i)*DD + j];
            #pragma unroll 4
            for (int r = rh*16; r < rh*16 + 16; r++) {
                float a = 0.f;
                #pragma unroll
                for (int b = 0; b < BB; b++) a += sm[r*BB + b] * wr[b];
                g_fullW[((size_t)r*DD + i)*DD + j] = a;
            }
        }
        __threadfence();
        __syncthreads();
        if (tid == 0) atomicAdd(&g_bdone, 1);
    }

    // ---- ticket loop: self tiles (0..127) first, then gated edge tiles ----
    const int tyP = wid & 7, txH = wid >> 3;
    const int ty = 2*tyP + (lane >> 4);        // 0..15 -> rows 4ty..4ty+3
    const int tx = txH*16 + (lane & 15);       // 0..31 -> cols 4tx..4tx+3
    const float* last_w = (const float*)0;
    bool edges_ok = false;
    int ntiles = 0;

    for (;;) {
        __syncthreads();                       // previous tile fully consumed
        if (tid == 0) s_misc[0] = (int)atomicAdd(&g_ticket, 1u);
        __syncthreads();
        const int t = s_misc[0];
        const bool is_self = (t < 128);

        int rel = 0, base, cnt, off = 0;
        if (is_self) { base = t*TROWS; cnt = NN; }
        else {
            if (!edges_ok) {                   // gate: scatter + basis complete
                if (tid == 0)
                    while (ld_cg(&g_sdone) < 32 || ld_cg(&g_bdone) < 116)
                        __nanosleep(64);
                __syncthreads();
                edges_ok = true;
                ntiles = g_ntiles;
            }
            if (t - 128 >= ntiles) break;
            const int tt = g_tiles[t - 128];
            rel = tt >> 8; base = (tt & 255)*TROWS;
            cnt = g_relcnt[rel]; off = g_reloff[rel];
        }

        if (tid < TROWS) {                     // per-row metadata
            if (is_self) {
                s_src[tid] = base + tid; s_tgt[tid] = base + tid; s_inv[tid] = 1.f;
            } else {
                const int le = base + tid;
                const bool v = le < cnt;
                const int e = g_sorted[off + (v ? le : base)];
                const int sN = g_src[e], tN = g_tgt[e];
                s_src[tid] = sN; s_tgt[tid] = tN;
                s_inv[tid] = v ? 1.0f/(float)g_comb[tN*RR + rel] : 0.f;
            }
        }
        // stage W [128k x 128c] (stride WS), skipped when unchanged
        const float* wsrc = is_self ? sw : g_fullW + (size_t)rel*DD*DD;
        if (wsrc != last_w) {
            if (is_self) {                     // transpose sw on the fly
                #pragma unroll
                for (int p = 0; p < 8; p++) {
                    const int m = tid + p*NTHR;          // < 4096
                    const int jr = m & 127, k4 = m >> 7;
                    const float4 v = ((const float4*)sw)[jr*32 + k4];
                    sW[(4*k4 + 0)*WS + jr] = v.x;
                    sW[(4*k4 + 1)*WS + jr] = v.y;
                    sW[(4*k4 + 2)*WS + jr] = v.z;
                    sW[(4*k4 + 3)*WS + jr] = v.w;
                }
            } else {
                #pragma unroll
                for (int p = 0; p < 8; p++) {
                    const int m = tid + p*NTHR;          // < 4096
                    const int k = m >> 5, jj = m & 31;
                    ((float4*)sW)[k*33 + jj] = ((const float4*)wsrc)[m];
                }
            }
            last_w = wsrc;
        }
        __syncthreads();

        // gather x transposed: warp = (row-half, k-quarter-group), lane = row
        {
            const int half = wid & 1, kq = wid >> 1;
            const int r = 32*half + lane;
            const float4* ip = (const float4*)(inp + (size_t)s_src[r]*DD);
            #pragma unroll
            for (int p = 0; p < 4; p++) {
                const int k4 = kq + 8*p;
                const float4 v = ip[k4];
                xsT[(4*k4 + 0)*XT_STRIDE + r] = v.x;
                xsT[(4*k4 + 1)*XT_STRIDE + r] = v.y;
                xsT[(4*k4 + 2)*XT_STRIDE + r] = v.z;
                xsT[(4*k4 + 3)*XT_STRIDE + r] = v.w;
            }
        }
        __syncthreads();

        // warps whose 8 rows are all past cnt skip compute entirely
        if (is_self || base + tyP*8 < cnt) {
            u64 acc[8];                        // [row 0..3][colpair 0..1]
            #pragma unroll
            for (int q = 0; q < 8; q++) acc[q] = 0ull;

            const float* xp = xsT + 4*ty;
            const float* wp = sW + 4*tx;
            float4 xv = *(const float4*)xp;
            ulonglong2 wv = *(const ulonglong2*)wp;
            #pragma unroll 4
            for (int k = 0; k < DD; k++) {
                const float4     nxv = *(const float4*)(xp + (k+1)*XT_STRIDE);
                const ulonglong2 nwv = *(const ulonglong2*)(wp + (k+1)*WS);
                const u64 x0 = pack2(xv.x), x1 = pack2(xv.y);
                const u64 x2 = pack2(xv.z), x3 = pack2(xv.w);
                ffma2(acc[0], x0, wv.x); ffma2(acc[1], x0, wv.y);
                ffma2(acc[2], x1, wv.x); ffma2(acc[3], x1, wv.y);
                ffma2(acc[4], x2, wv.x); ffma2(acc[5], x2, wv.y);
                ffma2(acc[6], x3, wv.x); ffma2(acc[7], x3, wv.y);
                xv = nxv; wv = nwv;
            }

            // epilogue: one red.v4 per valid row (4 contiguous cols)
            float4 bb = make_float4(0.f, 0.f, 0.f, 0.f);
            if (is_self) bb = __ldg((const float4*)bias + tx);
            #pragma unroll
            for (int rr = 0; rr < 4; rr++) {
                const int r = 4*ty + rr;
                const float inv = s_inv[r];
                if (inv != 0.f) {
                    const float2 ca = unpack2(acc[2*rr]);
                    const float2 cb = unpack2(acc[2*rr + 1]);
                    red4(out + (size_t)s_tgt[r]*DD + 4*tx,
                         ca.x*inv + bb.x, ca.y*inv + bb.y,
                         cb.x*inv + bb.z, cb.y*inv + bb.w);
                }
            }
        }
    }

    // ---- epilogue: last block resets barrier slots for graph replay ----
    __threadfence();
    __syncthreads();
    if (tid == 0) {
        const int done = atomicAdd(&g_bar[7], 1);
        if (done == GRID - 1) {
            #pragma unroll
            for (int p = 0; p < 8; p++) g_bar[p] = 0;
            __threadfence();
        }
    }
}

// ---------------- launch ----------------
extern "C" void kernel_launch(void* const* d_in, const int* in_sizes, int n_in,
                              void* d_out, int out_size) {
    const float* inp    = (const float*)d_in[0];
    const void*  dep    = d_in[1];
    const void*  ei     = d_in[2];
    const float* weight = (const float*)d_in[3];
    const float* wcomp  = (const float*)d_in[4];
    const float* sw     = (const float*)d_in[5];
    const float* bias   = (const float*)d_in[6];
    float* out = (float*)d_out;

    const int SMEM = (17028 + 8772 + TROWS*3 + 8) * 4;   // ~104 KB
    cudaFuncSetAttribute(k_fused, cudaFuncAttributeMaxDynamicSharedMemorySize, SMEM);

    k_fused<<<GRID, NTHR, SMEM>>>(inp, dep, ei, weight, wcomp, sw, bias, out);
}